// round 7
// baseline (speedup 1.0000x reference)
#include <cuda_runtime.h>
#include <cstdint>

// Correlation cost volume: B=8, C=128, H=W=128, max_disp=4 -> 81 displacements.
// out[b, dy*9+dx, y, x] = (1/C) sum_c in1[b,c,y,x] * in2[b,c,y+dy-4,x+dx-4] (zero pad)
//
// R7: 18 warps (warp = (dy,row)), 4 px/thread -> 36 accumulator regs,
//     2 blocks/SM (36 warps). Even-dx packed fma.f32x2 with only aligned
//     register pairs (zero packing MOVs); odd-dx scalar FFMA. Quad-transposed
//     smem, conflict-free LDS.128; CH=4, 2-stage cp.async pipeline.

#define BB 8
#define CC 128
#define HH 128
#define WW 128
#define MD 4
#define ND 9
#define NDD 81
#define TY 2
#define CH 4
#define NCHUNK (CC / CH)        // 32
#define THREADS 576             // 18 warps: wid -> (dy = wid>>1, tr = wid&1)
#define S2_RI (TY + 2 * MD)     // 10

#define S1_ROWQ 32              // quads per in1 row
#define S2_ROWQ 34              // quads per padded in2 row (136 floats)
#define S1_Q (CH * TY * S1_ROWQ)        // 256
#define S2_Q (CH * S2_RI * S2_ROWQ)     // 1360
#define STAGE_Q (S1_Q + S2_Q)           // 1616
#define STAGE_BYTES (STAGE_Q * 16)      // 25856
#define SMEM_BYTES (2 * STAGE_BYTES)    // 51712

typedef unsigned long long u64t;

__device__ __forceinline__ void cp16(uint32_t dst, const float* src, int srcsz) {
    asm volatile("cp.async.cg.shared.global [%0], [%1], 16, %2;\n"
                 :: "r"(dst), "l"(src), "r"(srcsz));
}
__device__ __forceinline__ void cp_commit() {
    asm volatile("cp.async.commit_group;\n");
}
#define CP_WAIT(n) asm volatile("cp.async.wait_group %0;\n" :: "n"(n))

__device__ __forceinline__ u64t pk(float lo, float hi) {
    u64t r; asm("mov.b64 %0, {%1,%2};" : "=l"(r) : "f"(lo), "f"(hi)); return r;
}
__device__ __forceinline__ void upk(u64t v, float& lo, float& hi) {
    asm("mov.b64 {%0,%1}, %2;" : "=f"(lo), "=f"(hi) : "l"(v));
}
__device__ __forceinline__ void fma2(u64t& acc, u64t a, u64t b) {
    asm("fma.rn.f32x2 %0, %1, %2, %0;" : "+l"(acc) : "l"(a), "l"(b));
}

// Load channel-chunk cc into stage at shared byte address sbase.
__device__ __forceinline__ void load_chunk(
    int cc, uint32_t sbase,
    const float* __restrict__ in1, const float* __restrict__ in2,
    int b, int y0, int wid, int lane)
{
    const size_t cbase = (size_t)(b * CC + cc * CH) * (HH * WW);

    // in1: warps 0..7 each load one row (32 quads), transposed slots.
    if (wid < CH * TY) {
        int c = wid >> 1, row = wid & 1;
        const float* src = in1 + cbase + ((size_t)c * HH + y0 + row) * WW + 4 * lane;
        uint32_t slot = (uint32_t)((lane & 1) * 16 + (lane >> 1));
        cp16(sbase + 16u * ((uint32_t)(c * TY + row) * S1_ROWQ + slot), src, 16);
    }

    // in2: 40 rows over 18 warps; interior quads q = lane+1 (1..32).
    const int q = lane + 1;
    const uint32_t fslot = (uint32_t)((q & 1) * 17 + (q >> 1));
#pragma unroll
    for (int rr = 0; rr < 3; ++rr) {
        int r = wid + rr * 18;
        if (r < CH * S2_RI) {
            int c = (r >= 30) ? 3 : (r >= 20) ? 2 : (r >= 10) ? 1 : 0;
            int ri = r - 10 * c;
            int gy = y0 - MD + ri;
            int ok = ((unsigned)gy < HH) ? 16 : 0;
            const float* src = ok ? (in2 + cbase + ((size_t)c * HH + gy) * WW + 4 * lane)
                                  : in2;
            cp16(sbase + 16u * ((uint32_t)(S1_Q + (c * S2_RI + ri) * S2_ROWQ) + fslot),
                 src, ok);
        }
    }
}

__global__ __launch_bounds__(THREADS, 2)
void corr_kernel(const float* __restrict__ in1,
                 const float* __restrict__ in2,
                 float* __restrict__ out)
{
    extern __shared__ float sm[];
    const uint32_t smb = (uint32_t)__cvta_generic_to_shared(sm);

    const int y0 = blockIdx.x * TY;
    const int b  = blockIdx.y;

    const int tid  = threadIdx.x;
    const int wid  = tid >> 5;
    const int lane = tid & 31;
    const int dy   = wid >> 1;          // displacement row 0..8
    const int tr   = wid & 1;           // output row 0..1
    const int ri   = tr + dy;           // in2 tile row 0..9

    // pixel start: lanes 0..15 -> even quads, 16..31 -> odd quads (conflict-free)
    const int ps = (lane < 16) ? 8 * lane : 8 * (lane - 16) + 4;
    const int qf = ps >> 2;
    const int a_slot = (qf & 1) * 16 + (qf >> 1);
    const int f_s0 = ((qf    ) & 1) * 17 + ((qf    ) >> 1);
    const int f_s1 = ((qf + 1) & 1) * 17 + ((qf + 1) >> 1);
    const int f_s2 = ((qf + 2) & 1) * 17 + ((qf + 2) >> 1);

    // pre-zero always-padding edge quads (slots 0 and 33) in both stages
    if (tid < 2 * CH * S2_RI * 2) {     // 160
        int st  = (tid >= 80) ? 1 : 0;
        int rem = tid - 80 * st;
        float4* p = reinterpret_cast<float4*>(sm) +
                    (size_t)st * STAGE_Q + S1_Q + (rem >> 1) * S2_ROWQ + (rem & 1) * 33;
        *p = make_float4(0.f, 0.f, 0.f, 0.f);
    }

    u64t  ae[5][2];                     // even dx = 2*di, pixel pairs (0,1),(2,3)
    float ao[4][4];                     // odd  dx = 2*di+1, scalar per pixel
#pragma unroll
    for (int di = 0; di < 5; ++di) { ae[di][0] = 0ull; ae[di][1] = 0ull; }
#pragma unroll
    for (int di = 0; di < 4; ++di)
#pragma unroll
        for (int j = 0; j < 4; ++j) ao[di][j] = 0.0f;

    load_chunk(0, smb, in1, in2, b, y0, wid, lane);
    cp_commit();

    for (int cc = 0; cc < NCHUNK; ++cc) {
        CP_WAIT(0);
        __syncthreads();

        if (cc + 1 < NCHUNK)
            load_chunk(cc + 1, smb + ((cc + 1) & 1) * STAGE_BYTES,
                       in1, in2, b, y0, wid, lane);
        cp_commit();

        const float4* st4 = reinterpret_cast<const float4*>(sm) +
                            (size_t)(cc & 1) * STAGE_Q;
#pragma unroll
        for (int c = 0; c < CH; ++c) {
            const float4* ar = st4 + (c * TY + tr) * S1_ROWQ;
            const float4* fr = st4 + S1_Q + (c * S2_RI + ri) * S2_ROWQ;

            float4 A  = ar[a_slot];
            float4 F0 = fr[f_s0];
            float4 F1 = fr[f_s1];
            float4 F2 = fr[f_s2];

            // aligned pairs only -> no packing MOVs
            u64t pa0 = pk(A.x, A.y), pa1 = pk(A.z, A.w);
            u64t p0 = pk(F0.x, F0.y), p1 = pk(F0.z, F0.w);
            u64t p2 = pk(F1.x, F1.y), p3 = pk(F1.z, F1.w);
            u64t p4 = pk(F2.x, F2.y), p5 = pk(F2.z, F2.w);
            u64t p[6] = { p0, p1, p2, p3, p4, p5 };

#pragma unroll
            for (int di = 0; di < 5; ++di) {
                fma2(ae[di][0], pa0, p[di]);
                fma2(ae[di][1], pa1, p[di + 1]);
            }

            float fs[12] = { F0.x, F0.y, F0.z, F0.w,
                             F1.x, F1.y, F1.z, F1.w,
                             F2.x, F2.y, F2.z, F2.w };
            float as[4] = { A.x, A.y, A.z, A.w };
#pragma unroll
            for (int di = 0; di < 4; ++di)
#pragma unroll
                for (int j = 0; j < 4; ++j)
                    ao[di][j] = fmaf(as[j], fs[j + 2 * di + 1], ao[di][j]);
        }
    }

    // ---- epilogue: unpack, scale by 1/C, coalesced float4 stores ----
    const float sc = 1.0f / 128.0f;
    float* op = out + (((size_t)b * NDD + (size_t)dy * ND) * HH + (y0 + tr)) * WW + ps;

    float r[ND][4];
#pragma unroll
    for (int di = 0; di < 5; ++di) {
        upk(ae[di][0], r[2 * di][0], r[2 * di][1]);
        upk(ae[di][1], r[2 * di][2], r[2 * di][3]);
    }
#pragma unroll
    for (int di = 0; di < 4; ++di)
#pragma unroll
        for (int j = 0; j < 4; ++j)
            r[2 * di + 1][j] = ao[di][j];

#pragma unroll
    for (int dx = 0; dx < ND; ++dx) {
        float4 v = { r[dx][0] * sc, r[dx][1] * sc, r[dx][2] * sc, r[dx][3] * sc };
        *reinterpret_cast<float4*>(op + (size_t)dx * (HH * WW)) = v;
    }
}

extern "C" void kernel_launch(void* const* d_in, const int* in_sizes, int n_in,
                              void* d_out, int out_size)
{
    (void)in_sizes; (void)n_in; (void)out_size;
    cudaFuncSetAttribute(corr_kernel,
                         cudaFuncAttributeMaxDynamicSharedMemorySize, SMEM_BYTES);
    const float* in1 = (const float*)d_in[0];
    const float* in2 = (const float*)d_in[1];
    float* out = (float*)d_out;
    corr_kernel<<<dim3(HH / TY, BB), THREADS, SMEM_BYTES>>>(in1, in2, out);
}

// round 9
// speedup vs baseline: 1.8990x; 1.8990x over previous
#include <cuda_runtime.h>
#include <cstdint>

// Correlation cost volume: B=8, C=128, H=W=128, max_disp=4 -> 81 displacements.
// out[b, dy*9+dx, y, x] = (1/C) sum_c in1[b,c,y,x] * in2[b,c,y+dy-4,x+dx-4] (zero pad)
//
// R8 = R3 tiling + zero-MOV operand scheme:
//  - 288 threads, 9 warps (warp = dy), thread = 8 px (lane>>4 = row, lane&15 = xblk)
//  - even dx: fma.rn.f32x2 on aligned register pairs only (no packing MOVs)
//  - odd dx: scalar FFMA on float4 components (no MOVs)
//  - quad-transposed smem, conflict-free LDS.128; CH=8, 2-stage cp.async.

#define BB 8
#define CC 128
#define HH 128
#define WW 128
#define MD 4
#define ND 9
#define NDD 81
#define TY 2
#define CH 8
#define NCHUNK (CC / CH)        // 16
#define THREADS 288             // 9 warps
#define S2_RI (TY + 2 * MD)     // 10

#define S1_ROWQ 32              // quads per in1 row
#define S2_ROWQ 34              // quads per padded in2 row (136 floats)
#define S1_Q (CH * TY * S1_ROWQ)        // 512
#define S2_Q (CH * S2_RI * S2_ROWQ)     // 2720
#define STAGE_Q (S1_Q + S2_Q)           // 3232
#define STAGE_BYTES (STAGE_Q * 16)      // 51712
#define SMEM_BYTES (2 * STAGE_BYTES)    // 103424

typedef unsigned long long u64t;

__device__ __forceinline__ void cp16(uint32_t dst, const float* src, int srcsz) {
    asm volatile("cp.async.cg.shared.global [%0], [%1], 16, %2;\n"
                 :: "r"(dst), "l"(src), "r"(srcsz));
}
__device__ __forceinline__ void cp_commit() {
    asm volatile("cp.async.commit_group;\n");
}
#define CP_WAIT(n) asm volatile("cp.async.wait_group %0;\n" :: "n"(n))

__device__ __forceinline__ u64t pk(float lo, float hi) {
    u64t r; asm("mov.b64 %0, {%1,%2};" : "=l"(r) : "f"(lo), "f"(hi)); return r;
}
__device__ __forceinline__ void upk(u64t v, float& lo, float& hi) {
    asm("mov.b64 {%0,%1}, %2;" : "=f"(lo), "=f"(hi) : "l"(v));
}
__device__ __forceinline__ void fma2(u64t& acc, u64t a, u64t b) {
    asm("fma.rn.f32x2 %0, %1, %2, %0;" : "+l"(acc) : "l"(a), "l"(b));
}

// Load channel-chunk cc into stage at shared byte address sbase.
__device__ __forceinline__ void load_chunk(
    int cc, uint32_t sbase,
    const float* __restrict__ in1, const float* __restrict__ in2,
    int b, int y0, int w, int lane)
{
    const size_t cbase = (size_t)(b * CC + cc * CH) * (HH * WW);
    const float* g1 = in1 + cbase;
    const float* g2 = in2 + cbase;

    // in1: 16 rows of 32 quads; lane -> quad = lane
    {
        const uint32_t dslot = (uint32_t)((lane & 1) * 16 + (lane >> 1));
#pragma unroll
        for (int r = w; r < CH * TY; r += ND) {
            int c = r >> 1, row = r & 1;
            const float* src = g1 + ((size_t)c * HH + y0 + row) * WW + 4 * lane;
            cp16(sbase + 16u * ((uint32_t)(c * TY + row) * S1_ROWQ + dslot), src, 16);
        }
    }

    // in2: 80 rows, interior quads q = lane+1 (1..32)
    {
        const int q = lane + 1;
        const uint32_t fslot = (uint32_t)((q & 1) * 17 + (q >> 1));
        const uint32_t s2b = sbase + 16u * S1_Q;
        int ri = w, c = 0;      // enumerate r = w + 9k as (c, ri), ri in [0,10)
        if (ri >= S2_RI) { ri -= S2_RI; ++c; }
        while (c < CH) {
            int gy = y0 - MD + ri;
            int ok = ((unsigned)gy < HH) ? 16 : 0;
            const float* src = ok ? (g2 + ((size_t)c * HH + gy) * WW + 4 * lane) : g2;
            cp16(s2b + 16u * ((uint32_t)(c * S2_RI + ri) * S2_ROWQ + fslot), src, ok);
            ri += ND;
            if (ri >= S2_RI) { ri -= S2_RI; ++c; }
        }
    }
}

__global__ __launch_bounds__(THREADS, 2)
void corr_kernel(const float* __restrict__ in1,
                 const float* __restrict__ in2,
                 float* __restrict__ out)
{
    extern __shared__ float sm[];
    const uint32_t smb = (uint32_t)__cvta_generic_to_shared(sm);

    const int y0 = blockIdx.x * TY;
    const int b  = blockIdx.y;

    const int tid  = threadIdx.x;
    const int w    = tid >> 5;          // dy index 0..8
    const int lane = tid & 31;
    const int tr   = lane >> 4;         // output row 0..1
    const int lb   = lane & 15;         // pixels x = 8*lb + j
    const int ri   = tr + w;            // in2 tile row 0..9

    // pre-zero always-padding edge quads (slots 0 and 33) in both stages
    for (int i = tid; i < 2 * CH * S2_RI * 2; i += THREADS) {   // 320
        int st  = i / (CH * S2_RI * 2);
        int rem = i - st * (CH * S2_RI * 2);
        float4* p = reinterpret_cast<float4*>(sm) +
                    (size_t)st * STAGE_Q + S1_Q + (rem >> 1) * S2_ROWQ + (rem & 1) * 33;
        *p = make_float4(0.f, 0.f, 0.f, 0.f);
    }

    u64t  ae[5][4];                     // even dx = 2*di, pixel pairs (2jj,2jj+1)
    float ao[4][8];                     // odd  dx = 2*di+1, scalar per pixel
#pragma unroll
    for (int di = 0; di < 5; ++di)
#pragma unroll
        for (int jj = 0; jj < 4; ++jj) ae[di][jj] = 0ull;
#pragma unroll
    for (int di = 0; di < 4; ++di)
#pragma unroll
        for (int j = 0; j < 8; ++j) ao[di][j] = 0.0f;

    load_chunk(0, smb, in1, in2, b, y0, w, lane);
    cp_commit();

    for (int cc = 0; cc < NCHUNK; ++cc) {
        CP_WAIT(0);          // chunk cc resident (this thread's copies)
        __syncthreads();     // all copies visible; prev compute finished (WAR)

        if (cc + 1 < NCHUNK)
            load_chunk(cc + 1, smb + ((cc + 1) & 1) * STAGE_BYTES,
                       in1, in2, b, y0, w, lane);
        cp_commit();

        const float4* st4 = reinterpret_cast<const float4*>(sm) +
                            (size_t)(cc & 1) * STAGE_Q;
#pragma unroll
        for (int c = 0; c < CH; ++c) {
            const float4* ar = st4 + (c * TY + tr) * S1_ROWQ;
            const float4* fr = st4 + S1_Q + (c * S2_RI + ri) * S2_ROWQ;

            float4 A0 = ar[lb];             // pixels 8lb+0..3
            float4 A1 = ar[16 + lb];        // pixels 8lb+4..7
            float4 F0 = fr[lb];             // f[0..3]
            float4 F1 = fr[17 + lb];        // f[4..7]
            float4 F2 = fr[lb + 1];         // f[8..11]
            float4 F3 = fr[17 + lb + 1];    // f[12..15]

            // aligned register pairs only -> no packing MOVs
            u64t pa[4] = { pk(A0.x, A0.y), pk(A0.z, A0.w),
                           pk(A1.x, A1.y), pk(A1.z, A1.w) };
            u64t P[8]  = { pk(F0.x, F0.y), pk(F0.z, F0.w),
                           pk(F1.x, F1.y), pk(F1.z, F1.w),
                           pk(F2.x, F2.y), pk(F2.z, F2.w),
                           pk(F3.x, F3.y), pk(F3.z, F3.w) };

#pragma unroll
            for (int di = 0; di < 5; ++di)      // even dx = 2*di
#pragma unroll
                for (int jj = 0; jj < 4; ++jj)
                    fma2(ae[di][jj], pa[jj], P[jj + di]);

            float a[8]  = { A0.x, A0.y, A0.z, A0.w, A1.x, A1.y, A1.z, A1.w };
            float f[16] = { F0.x, F0.y, F0.z, F0.w, F1.x, F1.y, F1.z, F1.w,
                            F2.x, F2.y, F2.z, F2.w, F3.x, F3.y, F3.z, F3.w };
#pragma unroll
            for (int di = 0; di < 4; ++di)      // odd dx = 2*di+1
#pragma unroll
                for (int j = 0; j < 8; ++j)
                    ao[di][j] = fmaf(a[j], f[j + 2 * di + 1], ao[di][j]);
        }
    }

    // ---- epilogue: unpack, scale by 1/C, coalesced float4 stores ----
    const float sc = 1.0f / 128.0f;
    float* op = out + (((size_t)b * NDD + (size_t)w * ND) * HH + (y0 + tr)) * WW + lb * 8;

    float r[ND][8];
#pragma unroll
    for (int di = 0; di < 5; ++di)
#pragma unroll
        for (int jj = 0; jj < 4; ++jj)
            upk(ae[di][jj], r[2 * di][2 * jj], r[2 * di][2 * jj + 1]);
#pragma unroll
    for (int di = 0; di < 4; ++di)
#pragma unroll
        for (int j = 0; j < 8; ++j)
            r[2 * di + 1][j] = ao[di][j];

#pragma unroll
    for (int dx = 0; dx < ND; ++dx) {
        float4 v0 = { r[dx][0] * sc, r[dx][1] * sc, r[dx][2] * sc, r[dx][3] * sc };
        float4 v1 = { r[dx][4] * sc, r[dx][5] * sc, r[dx][6] * sc, r[dx][7] * sc };
        *reinterpret_cast<float4*>(op + (size_t)dx * (HH * WW))     = v0;
        *reinterpret_cast<float4*>(op + (size_t)dx * (HH * WW) + 4) = v1;
    }
}

extern "C" void kernel_launch(void* const* d_in, const int* in_sizes, int n_in,
                              void* d_out, int out_size)
{
    (void)in_sizes; (void)n_in; (void)out_size;
    cudaFuncSetAttribute(corr_kernel,
                         cudaFuncAttributeMaxDynamicSharedMemorySize, SMEM_BYTES);
    const float* in1 = (const float*)d_in[0];
    const float* in2 = (const float*)d_in[1];
    float* out = (float*)d_out;
    corr_kernel<<<dim3(HH / TY, BB), THREADS, SMEM_BYTES>>>(in1, in2, out);
}